// round 7
// baseline (speedup 1.0000x reference)
#include <cuda_runtime.h>
#include <cuda_bf16.h>

// SingleLIFLayer: V <- V + (dt/tau)*(V_reset - V + I); spike = V >= V_th; reset.
// T=1024 sequential steps, N=65536 independent neurons. DRAM-bound streaming:
// 256 MB read + 256 MB write. Floor ~72 us at ~7.5 TB/s effective.
//
// V3: float4 (4 neurons/thread) + double-buffered software pipeline so the
// next batch's LDG.128s are in flight during compute+stores of the current
// batch -> continuous read stream, no per-warp load/store phase bursts.

#define LIF_T   1024
#define LIF_N4  16384          // N / 4 float4 columns
#define THREADS 128
#define TBATCH  8              // timesteps per pipeline stage
#define NBATCH  (LIF_T / TBATCH)

__global__ __launch_bounds__(THREADS)
void lif_kernel(const float4* __restrict__ in, float4* __restrict__ out) {
    const int c = blockIdx.x * THREADS + threadIdx.x;   // float4 column
    const float alpha = 0.05f;
    const float vth   = 1.0f;

    float Vx = 0.0f, Vy = 0.0f, Vz = 0.0f, Vw = 0.0f;

    const float4* __restrict__ ip = in  + c;
    float4*       __restrict__ sp = out + c;

    float4 buf[2][TBATCH];

    // Prologue: issue loads for batch 0.
    #pragma unroll
    for (int k = 0; k < TBATCH; ++k)
        buf[0][k] = __ldcs(ip + k * LIF_N4);

    #pragma unroll 1
    for (int tb = 0; tb < NBATCH; ++tb) {
        const int cb = tb & 1;
        const int nb = cb ^ 1;

        // Prefetch next batch (predicated off on the last iteration) BEFORE
        // touching this batch's data -> reads stay in flight through the
        // compute/store phase below.
        if (tb + 1 < NBATCH) {
            const float4* ipn = ip + (tb + 1) * (TBATCH * LIF_N4);
            #pragma unroll
            for (int k = 0; k < TBATCH; ++k)
                buf[nb][k] = __ldcs(ipn + k * LIF_N4);
        }

        // Compute 8 timesteps x 4 independent neuron lanes; store each
        // timestep as one STG.128 streaming store.
        float4* spb = sp + tb * (TBATCH * LIF_N4);
        #pragma unroll
        for (int k = 0; k < TBATCH; ++k) {
            const float4 I = buf[cb][k];
            float4 s;

            Vx = fmaf(alpha, I.x - Vx, Vx);
            bool bx = (Vx >= vth); s.x = bx ? 1.0f : 0.0f; if (bx) Vx = 0.0f;

            Vy = fmaf(alpha, I.y - Vy, Vy);
            bool by = (Vy >= vth); s.y = by ? 1.0f : 0.0f; if (by) Vy = 0.0f;

            Vz = fmaf(alpha, I.z - Vz, Vz);
            bool bz = (Vz >= vth); s.z = bz ? 1.0f : 0.0f; if (bz) Vz = 0.0f;

            Vw = fmaf(alpha, I.w - Vw, Vw);
            bool bw = (Vw >= vth); s.w = bw ? 1.0f : 0.0f; if (bw) Vw = 0.0f;

            __stcs(spb + k * LIF_N4, s);
        }
    }
}

extern "C" void kernel_launch(void* const* d_in, const int* in_sizes, int n_in,
                              void* d_out, int out_size) {
    const float4* input = (const float4*)d_in[0];
    float4* spikes = (float4*)d_out;

    const int grid = LIF_N4 / THREADS;   // 128 CTAs x 128 threads = 16384 threads
    lif_kernel<<<grid, THREADS>>>(input, spikes);
}

// round 8
// speedup vs baseline: 2.4296x; 2.4296x over previous
#include <cuda_runtime.h>
#include <cuda_bf16.h>

// SingleLIFLayer: V <- V + (dt/tau)*(V_reset - V + I); spike = V >= V_th; reset.
// T=1024 sequential steps, N=65536 independent neurons. DRAM-bound streaming:
// 256 MB read + 256 MB write.
//
// V4 = R5 winner (scalar, 512x128, TBATCH=16 front-batched -> MLP16, 62% DRAM)
//      + double-buffered prefetch: batch i+1 loads issue BEFORE batch i's
//      compute+stores, closing the per-warp read-issue gap.
// Deliberately scalar: R7 showed float4 (16K threads, 4 warps/SM) collapses
// to 27% DRAM, and big float4 buffers get re-ordered by ptxas (regs=42 != 64).

#define LIF_T   1024
#define LIF_N   65536
#define THREADS 128
#define TBATCH  16
#define NBATCH  (LIF_T / TBATCH)

__global__ __launch_bounds__(THREADS)
void lif_kernel(const float* __restrict__ in, float* __restrict__ out) {
    const int n = blockIdx.x * THREADS + threadIdx.x;   // neuron index
    const float alpha = 0.05f;   // dt/tau = 1/20
    const float vth   = 1.0f;

    float V = 0.0f;              // V_reset = 0

    const float* __restrict__ ip = in  + n;
    float*       __restrict__ sp = out + n;

    float bufA[TBATCH];
    float bufB[TBATCH];

    // Prologue: loads for batch 0 into A.
    #pragma unroll
    for (int k = 0; k < TBATCH; ++k)
        bufA[k] = __ldcs(ip + k * LIF_N);

    #pragma unroll 1
    for (int tb = 0; tb < NBATCH; tb += 2) {
        // --- consume A, prefetch into B ---
        {
            const float* ipn = ip + (tb + 1) * (TBATCH * LIF_N);
            if (tb + 1 < NBATCH) {
                #pragma unroll
                for (int k = 0; k < TBATCH; ++k)
                    bufB[k] = __ldcs(ipn + k * LIF_N);
            }
            float* spb = sp + tb * (TBATCH * LIF_N);
            #pragma unroll
            for (int k = 0; k < TBATCH; ++k) {
                V = fmaf(alpha, bufA[k] - V, V);
                bool s = (V >= vth);
                __stcs(spb + k * LIF_N, s ? 1.0f : 0.0f);
                if (s) V = 0.0f;
            }
        }
        // --- consume B, prefetch into A ---
        {
            const float* ipn = ip + (tb + 2) * (TBATCH * LIF_N);
            if (tb + 2 < NBATCH) {
                #pragma unroll
                for (int k = 0; k < TBATCH; ++k)
                    bufA[k] = __ldcs(ipn + k * LIF_N);
            }
            float* spb = sp + (tb + 1) * (TBATCH * LIF_N);
            #pragma unroll
            for (int k = 0; k < TBATCH; ++k) {
                V = fmaf(alpha, bufB[k] - V, V);
                bool s = (V >= vth);
                __stcs(spb + k * LIF_N, s ? 1.0f : 0.0f);
                if (s) V = 0.0f;
            }
        }
    }
}

extern "C" void kernel_launch(void* const* d_in, const int* in_sizes, int n_in,
                              void* d_out, int out_size) {
    const float* input = (const float*)d_in[0];
    float* spikes = (float*)d_out;

    const int grid = LIF_N / THREADS;   // 512 CTAs x 128 threads = 65536 threads
    lif_kernel<<<grid, THREADS>>>(input, spikes);
}